// round 2
// baseline (speedup 1.0000x reference)
#include <cuda_runtime.h>
#include <cuda_bf16.h>

// Problem dims (fixed by the dataset)
#define NROWS 16384
#define FDIM  1024
#define HDIM  256

// ---------------- device scratch (static allocation is the allowed path) ----
__device__ float  g_buf[NROWS * HDIM];           // 16 MB: g = X@We + be
__device__ float2 cm_buf[NROWS];                 // {c_j, (s_j != p) ? 1 : 0}
__device__ float  mse_partials[(NROWS / 64) * (FDIM / 64)];  // 4096
__device__ float  pair_partials[(NROWS / 256) * 8];          // 512

// ============================================================================
// GEMM1: g[NROWS,HDIM] = X[NROWS,FDIM] @ We[FDIM,HDIM] + be
// 64x64 tile, BK=16, 256 threads, 4x4 register tile per thread.
// ============================================================================
__global__ void __launch_bounds__(256) gemm1_kernel(
    const float* __restrict__ X, const float* __restrict__ We,
    const float* __restrict__ be)
{
    constexpr int BM = 64, BN = 64, BK = 16, TM = 4, TN = 4;
    __shared__ float As[BK][BM];
    __shared__ float Bs[BK][BN];

    const int tid = threadIdx.x;
    const int tx  = tid % (BN / TN);   // 0..15
    const int ty  = tid / (BN / TN);   // 0..15
    const int rowBase = blockIdx.y * BM;
    const int colBase = blockIdx.x * BN;

    float acc[TM][TN] = {};

    for (int k0 = 0; k0 < FDIM; k0 += BK) {
        #pragma unroll
        for (int i = tid; i < BM * BK; i += 256) {
            int r = i / BK, c = i % BK;
            As[c][r] = X[(size_t)(rowBase + r) * FDIM + k0 + c];
        }
        #pragma unroll
        for (int i = tid; i < BK * BN; i += 256) {
            int r = i / BN, c = i % BN;
            Bs[r][c] = We[(size_t)(k0 + r) * HDIM + colBase + c];
        }
        __syncthreads();
        #pragma unroll
        for (int kk = 0; kk < BK; kk++) {
            float a[TM], b[TN];
            #pragma unroll
            for (int i = 0; i < TM; i++) a[i] = As[kk][ty * TM + i];
            #pragma unroll
            for (int j = 0; j < TN; j++) b[j] = Bs[kk][tx * TN + j];
            #pragma unroll
            for (int i = 0; i < TM; i++)
                #pragma unroll
                for (int j = 0; j < TN; j++)
                    acc[i][j] = fmaf(a[i], b[j], acc[i][j]);
        }
        __syncthreads();
    }

    #pragma unroll
    for (int j = 0; j < TN; j++) {
        float bias = be[colBase + tx * TN + j];
        #pragma unroll
        for (int i = 0; i < TM; i++) {
            int r = rowBase + ty * TM + i;
            int c = colBase + tx * TN + j;
            g_buf[(size_t)r * HDIM + c] = acc[i][j] + bias;
        }
    }
}

// ============================================================================
// GEMM2 (fused): rec = g @ Wd + bd; accumulate sum((rec - X)^2) per block.
// Never materializes rec. Deterministic block-tree partial sum.
// ============================================================================
__global__ void __launch_bounds__(256) gemm2_mse_kernel(
    const float* __restrict__ Wd, const float* __restrict__ bd,
    const float* __restrict__ X)
{
    constexpr int BM = 64, BN = 64, BK = 16, TM = 4, TN = 4;
    __shared__ float As[BK][BM];
    __shared__ float Bs[BK][BN];
    __shared__ float red[256];

    const int tid = threadIdx.x;
    const int tx  = tid % (BN / TN);
    const int ty  = tid / (BN / TN);
    const int rowBase = blockIdx.y * BM;
    const int colBase = blockIdx.x * BN;

    float acc[TM][TN] = {};

    for (int k0 = 0; k0 < HDIM; k0 += BK) {
        #pragma unroll
        for (int i = tid; i < BM * BK; i += 256) {
            int r = i / BK, c = i % BK;
            As[c][r] = g_buf[(size_t)(rowBase + r) * HDIM + k0 + c];
        }
        #pragma unroll
        for (int i = tid; i < BK * BN; i += 256) {
            int r = i / BN, c = i % BN;
            Bs[r][c] = Wd[(size_t)(k0 + r) * FDIM + colBase + c];
        }
        __syncthreads();
        #pragma unroll
        for (int kk = 0; kk < BK; kk++) {
            float a[TM], b[TN];
            #pragma unroll
            for (int i = 0; i < TM; i++) a[i] = As[kk][ty * TM + i];
            #pragma unroll
            for (int j = 0; j < TN; j++) b[j] = Bs[kk][tx * TN + j];
            #pragma unroll
            for (int i = 0; i < TM; i++)
                #pragma unroll
                for (int j = 0; j < TN; j++)
                    acc[i][j] = fmaf(a[i], b[j], acc[i][j]);
        }
        __syncthreads();
    }

    // Epilogue: (acc + bd[col] - X[row,col])^2, thread-local sum
    float local = 0.f;
    #pragma unroll
    for (int j = 0; j < TN; j++) {
        int c = colBase + tx * TN + j;
        float bias = bd[c];
        #pragma unroll
        for (int i = 0; i < TM; i++) {
            int r = rowBase + ty * TM + i;
            float d = acc[i][j] + bias - X[(size_t)r * FDIM + c];
            local = fmaf(d, d, local);
        }
    }

    red[tid] = local;
    __syncthreads();
    #pragma unroll
    for (int s = 128; s > 0; s >>= 1) {
        if (tid < s) red[tid] += red[tid + s];
        __syncthreads();
    }
    if (tid == 0)
        mse_partials[blockIdx.y * gridDim.x + blockIdx.x] = red[0];
}

// ============================================================================
// Critic: c[i] = dot(g[i,:], Wc) + bc; build cm_buf = {c_i, (s_i != p)}.
// One warp per row.
// ============================================================================
__global__ void __launch_bounds__(256) critic_kernel(
    const float* __restrict__ Wc, const float* __restrict__ bc,
    const int* __restrict__ s, const int* __restrict__ p_ptr)
{
    int warp = (blockIdx.x * blockDim.x + threadIdx.x) >> 5;
    int lane = threadIdx.x & 31;
    if (warp >= NROWS) return;
    const float* grow = g_buf + (size_t)warp * HDIM;
    float sum = 0.f;
    #pragma unroll
    for (int k = lane; k < HDIM; k += 32)
        sum = fmaf(grow[k], Wc[k], sum);
    #pragma unroll
    for (int off = 16; off > 0; off >>= 1)
        sum += __shfl_xor_sync(0xFFFFFFFFu, sum, off);
    if (lane == 0) {
        int p = *p_ptr;
        cm_buf[warp] = make_float2(sum + bc[0], (s[warp] != p) ? 1.0f : 0.0f);
    }
}

// ============================================================================
// Pairwise masked L1: total = sum_{i: s_i==p} sum_{j: s_j!=p} |c_i - c_j|
// Grid: (NROWS/256, 8); each thread handles one i over a 2048-wide j chunk.
// cm_buf (128 KB) stays L2-resident; inner loop = LDG.64 + FADD + FFMA.
// ============================================================================
__global__ void __launch_bounds__(256) pairwise_kernel(
    const int* __restrict__ s, const int* __restrict__ p_ptr)
{
    constexpr int JCHUNK = NROWS / 8;   // 2048
    const int i  = blockIdx.x * 256 + threadIdx.x;
    const int j0 = blockIdx.y * JCHUNK;
    const int p  = *p_ptr;

    float acc = 0.f;
    if (s[i] == p) {
        const float ci = cm_buf[i].x;
        #pragma unroll 8
        for (int j = j0; j < j0 + JCHUNK; j++) {
            float2 v = __ldg(&cm_buf[j]);
            acc = fmaf(v.y, fabsf(ci - v.x), acc);
        }
    }

    __shared__ float red[256];
    red[threadIdx.x] = acc;
    __syncthreads();
    #pragma unroll
    for (int st = 128; st > 0; st >>= 1) {
        if (threadIdx.x < st) red[threadIdx.x] += red[threadIdx.x + st];
        __syncthreads();
    }
    if (threadIdx.x == 0)
        pair_partials[blockIdx.y * gridDim.x + blockIdx.x] = red[0];
}

// ============================================================================
// Finalize (1 block): reduce partials, count protected rows, write 4 outputs.
// ============================================================================
__global__ void __launch_bounds__(256) finalize_kernel(
    const int* __restrict__ s, const int* __restrict__ p_ptr,
    float* __restrict__ out)
{
    __shared__ double redd[256];
    __shared__ int    redi[256];
    const int tid = threadIdx.x;
    constexpr int N_MSE  = (NROWS / 64) * (FDIM / 64);
    constexpr int N_PAIR = (NROWS / 256) * 8;

    double m = 0.0;
    for (int i = tid; i < N_MSE; i += 256) m += (double)mse_partials[i];
    redd[tid] = m;
    __syncthreads();
    for (int st = 128; st > 0; st >>= 1) {
        if (tid < st) redd[tid] += redd[tid + st];
        __syncthreads();
    }
    double mse_sum = redd[0];
    __syncthreads();

    double pr = 0.0;
    for (int i = tid; i < N_PAIR; i += 256) pr += (double)pair_partials[i];
    redd[tid] = pr;
    __syncthreads();
    for (int st = 128; st > 0; st >>= 1) {
        if (tid < st) redd[tid] += redd[tid + st];
        __syncthreads();
    }
    double pair_sum = redd[0];
    __syncthreads();

    const int p = *p_ptr;
    int cnt = 0;
    for (int i = tid; i < NROWS; i += 256) cnt += (s[i] == p) ? 1 : 0;
    redi[tid] = cnt;
    __syncthreads();
    for (int st = 128; st > 0; st >>= 1) {
        if (tid < st) redi[tid] += redi[tid + st];
        __syncthreads();
    }
    int count = redi[0];

    if (tid == 0) {
        out[0] = (float)(mse_sum / ((double)NROWS * (double)FDIM));
        out[1] = (float)NROWS;
        out[2] = (float)(pair_sum / (double)count);
        out[3] = (float)count;
    }
}

// ============================================================================
extern "C" void kernel_launch(void* const* d_in, const int* in_sizes, int n_in,
                              void* d_out, int out_size)
{
    const float* X  = (const float*)d_in[0];
    const float* We = (const float*)d_in[1];
    const float* be = (const float*)d_in[2];
    const float* Wd = (const float*)d_in[3];
    const float* bd = (const float*)d_in[4];
    const float* Wc = (const float*)d_in[5];
    const float* bc = (const float*)d_in[6];
    const int*   s  = (const int*)d_in[7];
    const int*   p  = (const int*)d_in[8];
    float* out = (float*)d_out;

    // GEMM1: g = X@We + be   [grid 4 x 256]
    gemm1_kernel<<<dim3(HDIM / 64, NROWS / 64), 256>>>(X, We, be);

    // GEMM2 fused MSE        [grid 16 x 256]
    gemm2_mse_kernel<<<dim3(FDIM / 64, NROWS / 64), 256>>>(Wd, bd, X);

    // Critic GEMV: 16384 warps -> 2048 blocks of 8 warps
    critic_kernel<<<(NROWS * 32) / 256, 256>>>(Wc, bc, s, p);

    // Pairwise masked L1
    pairwise_kernel<<<dim3(NROWS / 256, 8), 256>>>(s, p);

    // Finalize
    finalize_kernel<<<1, 256>>>(s, p, out);
}

// round 4
// speedup vs baseline: 4.4097x; 4.4097x over previous
#include <cuda_runtime.h>
#include <cuda_bf16.h>
#include <cstdint>

// Problem dims (fixed by the dataset)
#define NROWS 16384
#define FDIM  1024
#define HDIM  256

#define SMEM_SWIZZLE(off) ((off) ^ (((off) >> 3) & 0x70))

// ============================================================================
// Device scratch (static allocation is the allowed path)
// ============================================================================
__device__ __nv_bfloat16 X16_buf[NROWS * FDIM];    // 32 MB
__device__ __nv_bfloat16 WeT16_buf[HDIM * FDIM];   // [256][1024]: WeT[n][k] = We[k][n]
__device__ __nv_bfloat16 WdT16_buf[FDIM * HDIM];   // [1024][256]: WdT[n][k] = Wd[k][n]
__device__ __nv_bfloat16 g16_buf[NROWS * HDIM];    // 8 MB
__device__ float c_buf[NROWS];
__device__ float c_prot[NROWS];
__device__ float c_rest[NROWS];
__device__ int   np_g, nr_g;
__device__ float mse_partials[1024];
__device__ float pair_partials[256];

// ============================================================================
// mma.sync helpers (legal on base sm_103 target, unlike tcgen05)
// ============================================================================
__device__ __forceinline__ void ldmatrix_x4(uint32_t& r0, uint32_t& r1,
                                            uint32_t& r2, uint32_t& r3,
                                            uint32_t smem_addr) {
    asm volatile("ldmatrix.sync.aligned.m8n8.x4.shared.b16 {%0,%1,%2,%3}, [%4];"
                 : "=r"(r0), "=r"(r1), "=r"(r2), "=r"(r3) : "r"(smem_addr));
}
__device__ __forceinline__ void mma_16816(float& c0, float& c1, float& c2, float& c3,
                                          uint32_t a0, uint32_t a1, uint32_t a2, uint32_t a3,
                                          uint32_t b0, uint32_t b1) {
    asm volatile("mma.sync.aligned.m16n8k16.row.col.f32.bf16.bf16.f32 "
                 "{%0,%1,%2,%3}, {%4,%5,%6,%7}, {%8,%9}, {%0,%1,%2,%3};"
                 : "+f"(c0), "+f"(c1), "+f"(c2), "+f"(c3)
                 : "r"(a0), "r"(a1), "r"(a2), "r"(a3), "r"(b0), "r"(b1));
}
__device__ __forceinline__ uint32_t smem_u32_of(const void* p) {
    uint32_t a;
    asm("{ .reg .u64 t; cvta.to.shared.u64 t, %1; cvt.u32.u64 %0, t; }" : "=r"(a) : "l"(p));
    return a;
}

// ============================================================================
// Conversion kernels
// ============================================================================
__global__ void __launch_bounds__(256) conv_x_kernel(const float* __restrict__ X)
{
    int idx = blockIdx.x * 256 + threadIdx.x;           // one float4 each
    float4 v = ((const float4*)X)[idx];
    __nv_bfloat162 h0 = __floats2bfloat162_rn(v.x, v.y);
    __nv_bfloat162 h1 = __floats2bfloat162_rn(v.z, v.w);
    uint2 o;
    o.x = *reinterpret_cast<uint32_t*>(&h0);
    o.y = *reinterpret_cast<uint32_t*>(&h1);
    ((uint2*)X16_buf)[idx] = o;
}
__global__ void __launch_bounds__(256) conv_we_kernel(const float* __restrict__ We)
{
    int idx = blockIdx.x * 256 + threadIdx.x;           // 256*1024 total
    int n = idx >> 10, k = idx & 1023;
    WeT16_buf[idx] = __float2bfloat16_rn(We[(size_t)k * HDIM + n]);
}
__global__ void __launch_bounds__(256) conv_wd_kernel(const float* __restrict__ Wd)
{
    int idx = blockIdx.x * 256 + threadIdx.x;           // 1024*256 total
    int n = idx >> 8, k = idx & 255;
    WdT16_buf[idx] = __float2bfloat16_rn(Wd[(size_t)k * FDIM + n]);
}

// ============================================================================
// Shared mainloop core: per-CTA C[128,128] = A[128,K] @ B[128,K]^T (bf16)
// 8 warps as 4(M) x 2(N); warp tile 32x64. BK=64, SW-swizzled smem, ldmatrix.
// acc layout: acc[mf(2)][nf(8)][4]
// ============================================================================
struct MmaCtx {
    uint32_t sA, sB;   // smem u32 bases
    int wm, wn, lane;
};

__device__ __forceinline__ void mma_block_iter(
    const MmaCtx& ctx, float acc[2][8][4])
{
    const int lrow  = ctx.lane & 15;          // ldmatrix row-within-16
    const int lcolb = (ctx.lane >> 4) * 16;   // +16B for k8..15 half
    #pragma unroll
    for (int ks = 0; ks < 4; ks++) {
        const int kb = ks * 32;               // byte col offset of this k16
        uint32_t a[2][4], b[4][4];
        #pragma unroll
        for (int mf = 0; mf < 2; mf++) {
            int off = (ctx.wm * 32 + mf * 16 + lrow) * 128 + kb + lcolb;
            ldmatrix_x4(a[mf][0], a[mf][1], a[mf][2], a[mf][3],
                        ctx.sA + SMEM_SWIZZLE(off));
        }
        #pragma unroll
        for (int nf = 0; nf < 4; nf++) {
            int off = (ctx.wn * 64 + nf * 16 + lrow) * 128 + kb + lcolb;
            ldmatrix_x4(b[nf][0], b[nf][1], b[nf][2], b[nf][3],
                        ctx.sB + SMEM_SWIZZLE(off));
        }
        // b regs from A-style addressing of [N][K] tile:
        //  r0=(n0-7,k0-7) r1=(n8-15,k0-7) r2=(n0-7,k8-15) r3=(n8-15,k8-15)
        //  n8-frag(2*nf)   -> {r0, r2};  n8-frag(2*nf+1) -> {r1, r3}
        #pragma unroll
        for (int mf = 0; mf < 2; mf++)
            #pragma unroll
            for (int nf = 0; nf < 4; nf++) {
                mma_16816(acc[mf][2*nf][0], acc[mf][2*nf][1],
                          acc[mf][2*nf][2], acc[mf][2*nf][3],
                          a[mf][0], a[mf][1], a[mf][2], a[mf][3],
                          b[nf][0], b[nf][2]);
                mma_16816(acc[mf][2*nf+1][0], acc[mf][2*nf+1][1],
                          acc[mf][2*nf+1][2], acc[mf][2*nf+1][3],
                          a[mf][0], a[mf][1], a[mf][2], a[mf][3],
                          b[nf][1], b[nf][3]);
            }
    }
}

// Stage one 128x64 bf16 tile (row stride K_TOT elems) into swizzled smem.
__device__ __forceinline__ void stage_tile(
    char* dst, const __nv_bfloat16* __restrict__ src, int K_TOT, int k0, int tid)
{
    #pragma unroll
    for (int it = 0; it < 4; it++) {
        int idx = tid + it * 256;
        int row = idx >> 3, k8 = idx & 7;
        uint4 v = *(const uint4*)((const char*)src +
                   ((size_t)row * K_TOT + k0) * 2 + k8 * 16);
        *(uint4*)(dst + SMEM_SWIZZLE(row * 128 + k8 * 16)) = v;
    }
}

// ============================================================================
// GEMM1: g16 = bf16(X16 @ WeT^T + be).  grid = (2, 128), 256 threads.
// ============================================================================
__global__ void __launch_bounds__(256) gemm1_mma_kernel(const float* __restrict__ be)
{
    __shared__ alignas(1024) char As[128 * 128];   // 128 rows x 64 bf16
    __shared__ alignas(1024) char Bs[128 * 128];
    __shared__ float bias_s[128];

    const int tid = threadIdx.x;
    const int warp = tid >> 5;
    const int rowBase = blockIdx.y * 128;
    const int colBase = blockIdx.x * 128;
    if (tid < 128) bias_s[tid] = be[colBase + tid];

    MmaCtx ctx;
    ctx.sA = smem_u32_of(As); ctx.sB = smem_u32_of(Bs);
    ctx.wm = warp & 3; ctx.wn = warp >> 2; ctx.lane = tid & 31;

    float acc[2][8][4] = {};
    const __nv_bfloat16* Ag = X16_buf + (size_t)rowBase * FDIM;
    const __nv_bfloat16* Bg = WeT16_buf + (size_t)colBase * FDIM;

    for (int k0 = 0; k0 < FDIM; k0 += 64) {
        stage_tile(As, Ag, FDIM, k0, tid);
        stage_tile(Bs, Bg, FDIM, k0, tid);
        __syncthreads();
        mma_block_iter(ctx, acc);
        __syncthreads();
    }

    // Epilogue: + bias, convert to bf16, store g16
    const int g = ctx.lane >> 2, q = ctx.lane & 3;
    #pragma unroll
    for (int mf = 0; mf < 2; mf++) {
        #pragma unroll
        for (int nf = 0; nf < 8; nf++) {
            int lcol = ctx.wn * 64 + nf * 8 + q * 2;
            int col  = colBase + lcol;
            float b0 = bias_s[lcol], b1 = bias_s[lcol + 1];
            int row0 = rowBase + ctx.wm * 32 + mf * 16 + g;
            __nv_bfloat162 h0 = __floats2bfloat162_rn(acc[mf][nf][0] + b0,
                                                      acc[mf][nf][1] + b1);
            __nv_bfloat162 h1 = __floats2bfloat162_rn(acc[mf][nf][2] + b0,
                                                      acc[mf][nf][3] + b1);
            *(__nv_bfloat162*)(g16_buf + (size_t)row0 * HDIM + col) = h0;
            *(__nv_bfloat162*)(g16_buf + (size_t)(row0 + 8) * HDIM + col) = h1;
        }
    }
}

// ============================================================================
// GEMM2 fused MSE: rec = g16 @ WdT^T + bd; accum (rec - X)^2.
// grid = (8, 128), 256 threads.
// ============================================================================
__global__ void __launch_bounds__(256) gemm2_mma_kernel(
    const float* __restrict__ bd, const float* __restrict__ X)
{
    __shared__ alignas(1024) char As[128 * 128];
    __shared__ alignas(1024) char Bs[128 * 128];
    __shared__ float bias_s[128];
    __shared__ float red[256];

    const int tid = threadIdx.x;
    const int warp = tid >> 5;
    const int rowBase = blockIdx.y * 128;
    const int colBase = blockIdx.x * 128;
    if (tid < 128) bias_s[tid] = bd[colBase + tid];

    MmaCtx ctx;
    ctx.sA = smem_u32_of(As); ctx.sB = smem_u32_of(Bs);
    ctx.wm = warp & 3; ctx.wn = warp >> 2; ctx.lane = tid & 31;

    float acc[2][8][4] = {};
    const __nv_bfloat16* Ag = g16_buf + (size_t)rowBase * HDIM;
    const __nv_bfloat16* Bg = WdT16_buf + (size_t)colBase * HDIM;

    for (int k0 = 0; k0 < HDIM; k0 += 64) {
        stage_tile(As, Ag, HDIM, k0, tid);
        stage_tile(Bs, Bg, HDIM, k0, tid);
        __syncthreads();
        mma_block_iter(ctx, acc);
        __syncthreads();
    }

    // Fused epilogue: (acc + bd - X)^2
    const int g = ctx.lane >> 2, q = ctx.lane & 3;
    float local = 0.f;
    #pragma unroll
    for (int mf = 0; mf < 2; mf++) {
        #pragma unroll
        for (int nf = 0; nf < 8; nf++) {
            int lcol = ctx.wn * 64 + nf * 8 + q * 2;
            int col  = colBase + lcol;
            float b0 = bias_s[lcol], b1 = bias_s[lcol + 1];
            int row0 = rowBase + ctx.wm * 32 + mf * 16 + g;
            float2 x0 = *(const float2*)(X + (size_t)row0 * FDIM + col);
            float2 x1 = *(const float2*)(X + (size_t)(row0 + 8) * FDIM + col);
            float d0 = acc[mf][nf][0] + b0 - x0.x;
            float d1 = acc[mf][nf][1] + b1 - x0.y;
            float d2 = acc[mf][nf][2] + b0 - x1.x;
            float d3 = acc[mf][nf][3] + b1 - x1.y;
            local = fmaf(d0, d0, local);
            local = fmaf(d1, d1, local);
            local = fmaf(d2, d2, local);
            local = fmaf(d3, d3, local);
        }
    }

    red[tid] = local;
    __syncthreads();
    #pragma unroll
    for (int st = 128; st > 0; st >>= 1) {
        if (tid < st) red[tid] += red[tid + st];
        __syncthreads();
    }
    if (tid == 0) mse_partials[blockIdx.y * 8 + blockIdx.x] = red[0];
}

// ============================================================================
// Critic: c[i] = dot(g16[i,:], Wc) + bc.  One warp per row.
// ============================================================================
__global__ void __launch_bounds__(256) critic_kernel(
    const float* __restrict__ Wc, const float* __restrict__ bc)
{
    int row  = (blockIdx.x * 256 + threadIdx.x) >> 5;
    int lane = threadIdx.x & 31;
    int k0   = lane * 8;
    const __nv_bfloat162* gp =
        (const __nv_bfloat162*)(g16_buf + (size_t)row * HDIM + k0);
    float4 w0 = *(const float4*)(Wc + k0);
    float4 w1 = *(const float4*)(Wc + k0 + 4);
    float2 a0 = __bfloat1622float2(gp[0]);
    float2 a1 = __bfloat1622float2(gp[1]);
    float2 a2 = __bfloat1622float2(gp[2]);
    float2 a3 = __bfloat1622float2(gp[3]);
    float sum = a0.x * w0.x + a0.y * w0.y + a1.x * w0.z + a1.y * w0.w
              + a2.x * w1.x + a2.y * w1.y + a3.x * w1.z + a3.y * w1.w;
    #pragma unroll
    for (int off = 16; off > 0; off >>= 1)
        sum += __shfl_xor_sync(0xFFFFFFFFu, sum, off);
    if (lane == 0) c_buf[row] = sum + bc[0];
}

// ============================================================================
// Compaction: split c into c_prot (s==p) / c_rest (s!=p). 1 block, scan.
// ============================================================================
__global__ void __launch_bounds__(256) compact_kernel(
    const int* __restrict__ s, const int* __restrict__ p_ptr)
{
    __shared__ int scP[256], scR[256];
    const int tid = threadIdx.x;
    const int p = *p_ptr;
    const int base = tid * 64;

    int cp = 0;
    #pragma unroll 8
    for (int i = 0; i < 64; i++) cp += (s[base + i] == p) ? 1 : 0;
    scP[tid] = cp; scR[tid] = 64 - cp;
    __syncthreads();
    #pragma unroll
    for (int off = 1; off < 256; off <<= 1) {
        int vP = (tid >= off) ? scP[tid - off] : 0;
        int vR = (tid >= off) ? scR[tid - off] : 0;
        __syncthreads();
        scP[tid] += vP; scR[tid] += vR;
        __syncthreads();
    }
    if (tid == 255) { np_g = scP[255]; nr_g = scR[255]; }
    int oP = scP[tid] - cp;
    int oR = scR[tid] - (64 - cp);
    for (int i = 0; i < 64; i++) {
        int idx = base + i;
        float v = c_buf[idx];
        if (s[idx] == p) c_prot[oP++] = v;
        else             c_rest[oR++] = v;
    }
}

// ============================================================================
// Pairwise L1 over compacted arrays. grid (16,16), 4 i/thread, smem j tile.
// ============================================================================
__global__ void __launch_bounds__(256) pairwise_kernel()
{
    __shared__ float smj[1024];
    __shared__ float red[256];
    const int tid = threadIdx.x;
    const int np = np_g, nr = nr_g;
    const int iBase = blockIdx.x * 1024;
    const int jBase = blockIdx.y * 1024;

    float ci0 = 0.f, ci1 = 0.f, ci2 = 0.f, ci3 = 0.f;
    int i0 = iBase + tid, i1 = i0 + 256, i2 = i0 + 512, i3 = i0 + 768;
    bool v0 = i0 < np, v1 = i1 < np, v2 = i2 < np, v3 = i3 < np;
    if (v0) ci0 = c_prot[i0];
    if (v1) ci1 = c_prot[i1];
    if (v2) ci2 = c_prot[i2];
    if (v3) ci3 = c_prot[i3];

    #pragma unroll
    for (int t = tid; t < 1024; t += 256)
        smj[t] = (jBase + t < nr) ? c_rest[jBase + t] : 0.f;
    __syncthreads();

    int jn = nr - jBase;
    if (jn > 1024) jn = 1024;
    float a0 = 0.f, a1 = 0.f, a2 = 0.f, a3 = 0.f;
    for (int j = 0; j < jn; j++) {
        float cj = smj[j];
        a0 += fabsf(ci0 - cj);
        a1 += fabsf(ci1 - cj);
        a2 += fabsf(ci2 - cj);
        a3 += fabsf(ci3 - cj);
    }
    float local = (v0 ? a0 : 0.f) + (v1 ? a1 : 0.f) + (v2 ? a2 : 0.f) + (v3 ? a3 : 0.f);

    red[tid] = local;
    __syncthreads();
    #pragma unroll
    for (int st = 128; st > 0; st >>= 1) {
        if (tid < st) red[tid] += red[tid + st];
        __syncthreads();
    }
    if (tid == 0) pair_partials[blockIdx.y * 16 + blockIdx.x] = red[0];
}

// ============================================================================
// Finalize (1 block): reduce partials, write 4 outputs.
// ============================================================================
__global__ void __launch_bounds__(256) finalize_kernel(float* __restrict__ out)
{
    __shared__ double redd[256];
    const int tid = threadIdx.x;

    double m = 0.0;
    for (int i = tid; i < 1024; i += 256) m += (double)mse_partials[i];
    redd[tid] = m;
    __syncthreads();
    for (int st = 128; st > 0; st >>= 1) {
        if (tid < st) redd[tid] += redd[tid + st];
        __syncthreads();
    }
    double mse_sum = redd[0];
    __syncthreads();

    redd[tid] = (double)pair_partials[tid];
    __syncthreads();
    for (int st = 128; st > 0; st >>= 1) {
        if (tid < st) redd[tid] += redd[tid + st];
        __syncthreads();
    }
    double pair_sum = redd[0];

    if (tid == 0) {
        int count = np_g;
        out[0] = (float)(mse_sum / ((double)NROWS * (double)FDIM));
        out[1] = (float)NROWS;
        out[2] = (float)(pair_sum / (double)count);
        out[3] = (float)count;
    }
}

// ============================================================================
extern "C" void kernel_launch(void* const* d_in, const int* in_sizes, int n_in,
                              void* d_out, int out_size)
{
    const float* X  = (const float*)d_in[0];
    const float* We = (const float*)d_in[1];
    const float* be = (const float*)d_in[2];
    const float* Wd = (const float*)d_in[3];
    const float* bd = (const float*)d_in[4];
    const float* Wc = (const float*)d_in[5];
    const float* bc = (const float*)d_in[6];
    const int*   s  = (const int*)d_in[7];
    const int*   p  = (const int*)d_in[8];
    float* out = (float*)d_out;

    conv_x_kernel<<<(NROWS * FDIM / 4) / 256, 256>>>(X);
    conv_we_kernel<<<(HDIM * FDIM) / 256, 256>>>(We);
    conv_wd_kernel<<<(FDIM * HDIM) / 256, 256>>>(Wd);

    gemm1_mma_kernel<<<dim3(2, NROWS / 128), 256>>>(be);
    gemm2_mma_kernel<<<dim3(8, NROWS / 128), 256>>>(bd, X);

    critic_kernel<<<(NROWS * 32) / 256, 256>>>(Wc, bc);
    compact_kernel<<<1, 256>>>(s, p);
    pairwise_kernel<<<dim3(16, 16), 256>>>();
    finalize_kernel<<<1, 256>>>(out);
}

// round 7
// speedup vs baseline: 5.5151x; 1.2507x over previous
#include <cuda_runtime.h>
#include <cuda_bf16.h>
#include <cstdint>

// Problem dims (fixed by the dataset)
#define NROWS 16384
#define FDIM  1024
#define HDIM  256

#define SMEM_SWIZZLE(off) ((off) ^ (((off) >> 3) & 0x70))

// ============================================================================
// Device scratch (static allocation is the allowed path)
// ============================================================================
__device__ __nv_bfloat16 X16_buf[NROWS * FDIM];    // 32 MB
__device__ __nv_bfloat16 WeT16_buf[HDIM * FDIM];   // [256][1024]: WeT[n][k] = We[k][n]
__device__ __nv_bfloat16 WdT16_buf[FDIM * HDIM];   // [1024][256]: WdT[n][k] = Wd[k][n]
__device__ __nv_bfloat16 g16_buf[NROWS * HDIM];    // 8 MB
__device__ float c_buf[NROWS];
__device__ float c_prot[NROWS];
__device__ float c_rest[NROWS];
__device__ int   np_g, nr_g;
__device__ float mse_partials[1024];
__device__ float pair_partials[256];

// ============================================================================
// mma.sync / cp.async helpers (legal on base sm_103 target)
// ============================================================================
__device__ __forceinline__ void ldmatrix_x4(uint32_t& r0, uint32_t& r1,
                                            uint32_t& r2, uint32_t& r3,
                                            uint32_t smem_addr) {
    asm volatile("ldmatrix.sync.aligned.m8n8.x4.shared.b16 {%0,%1,%2,%3}, [%4];"
                 : "=r"(r0), "=r"(r1), "=r"(r2), "=r"(r3) : "r"(smem_addr));
}
__device__ __forceinline__ void mma_16816(float& c0, float& c1, float& c2, float& c3,
                                          uint32_t a0, uint32_t a1, uint32_t a2, uint32_t a3,
                                          uint32_t b0, uint32_t b1) {
    asm volatile("mma.sync.aligned.m16n8k16.row.col.f32.bf16.bf16.f32 "
                 "{%0,%1,%2,%3}, {%4,%5,%6,%7}, {%8,%9}, {%0,%1,%2,%3};"
                 : "+f"(c0), "+f"(c1), "+f"(c2), "+f"(c3)
                 : "r"(a0), "r"(a1), "r"(a2), "r"(a3), "r"(b0), "r"(b1));
}
__device__ __forceinline__ uint32_t smem_u32_of(const void* p) {
    uint32_t a;
    asm("{ .reg .u64 t; cvta.to.shared.u64 t, %1; cvt.u32.u64 %0, t; }" : "=r"(a) : "l"(p));
    return a;
}
__device__ __forceinline__ void cp_async16(uint32_t dst_smem, const void* src) {
    asm volatile("cp.async.cg.shared.global [%0], [%1], 16;"
                 :: "r"(dst_smem), "l"(src));
}
#define CP_COMMIT()  asm volatile("cp.async.commit_group;" ::: "memory")
#define CP_WAIT_1()  asm volatile("cp.async.wait_group 1;" ::: "memory")
#define CP_WAIT_0()  asm volatile("cp.async.wait_group 0;" ::: "memory")

// ============================================================================
// Conversion kernels
// ============================================================================
__global__ void __launch_bounds__(256) conv_x_kernel(const float* __restrict__ X)
{
    int idx = blockIdx.x * 256 + threadIdx.x;           // one float4 each
    float4 v = ((const float4*)X)[idx];
    __nv_bfloat162 h0 = __floats2bfloat162_rn(v.x, v.y);
    __nv_bfloat162 h1 = __floats2bfloat162_rn(v.z, v.w);
    uint2 o;
    o.x = *reinterpret_cast<uint32_t*>(&h0);
    o.y = *reinterpret_cast<uint32_t*>(&h1);
    ((uint2*)X16_buf)[idx] = o;
}
__global__ void __launch_bounds__(256) conv_w_kernel(
    const float* __restrict__ We, const float* __restrict__ Wd)
{
    int idx = blockIdx.x * 256 + threadIdx.x;           // 2*256*1024 total
    if (idx < HDIM * FDIM) {
        int n = idx >> 10, k = idx & 1023;
        WeT16_buf[idx] = __float2bfloat16_rn(We[(size_t)k * HDIM + n]);
    } else {
        int j = idx - HDIM * FDIM;
        int n = j >> 8, k = j & 255;
        WdT16_buf[j] = __float2bfloat16_rn(Wd[(size_t)k * FDIM + n]);
    }
}

// ============================================================================
// Warp-tile MMA compute over one staged (A,B) 128x64 slab pair.
// 8 warps as 4(M) x 2(N); warp tile 32x64. acc[mf(2)][nf(8)][4].
// ============================================================================
struct MmaCtx { int wm, wn, lane; };

__device__ __forceinline__ void mma_block_iter(
    const MmaCtx& ctx, uint32_t sA, uint32_t sB, float acc[2][8][4])
{
    const int lrow  = ctx.lane & 15;          // ldmatrix row-within-16
    const int lcolb = (ctx.lane >> 4) * 16;   // +16B for k8..15 half
    #pragma unroll
    for (int ks = 0; ks < 4; ks++) {
        const int kb = ks * 32;               // byte col offset of this k16
        uint32_t a[2][4], b[4][4];
        #pragma unroll
        for (int mf = 0; mf < 2; mf++) {
            int off = (ctx.wm * 32 + mf * 16 + lrow) * 128 + kb + lcolb;
            ldmatrix_x4(a[mf][0], a[mf][1], a[mf][2], a[mf][3],
                        sA + SMEM_SWIZZLE(off));
        }
        #pragma unroll
        for (int nf = 0; nf < 4; nf++) {
            int off = (ctx.wn * 64 + nf * 16 + lrow) * 128 + kb + lcolb;
            ldmatrix_x4(b[nf][0], b[nf][1], b[nf][2], b[nf][3],
                        sB + SMEM_SWIZZLE(off));
        }
        #pragma unroll
        for (int mf = 0; mf < 2; mf++)
            #pragma unroll
            for (int nf = 0; nf < 4; nf++) {
                mma_16816(acc[mf][2*nf][0], acc[mf][2*nf][1],
                          acc[mf][2*nf][2], acc[mf][2*nf][3],
                          a[mf][0], a[mf][1], a[mf][2], a[mf][3],
                          b[nf][0], b[nf][2]);
                mma_16816(acc[mf][2*nf+1][0], acc[mf][2*nf+1][1],
                          acc[mf][2*nf+1][2], acc[mf][2*nf+1][3],
                          a[mf][0], a[mf][1], a[mf][2], a[mf][3],
                          b[nf][1], b[nf][3]);
            }
    }
}

// Issue cp.async for one 128x64 bf16 tile (row stride K_TOT elems).
__device__ __forceinline__ void stage_tile_async(
    uint32_t dst_u32, const __nv_bfloat16* __restrict__ src,
    int K_TOT, int k0, int tid)
{
    #pragma unroll
    for (int it = 0; it < 4; it++) {
        int idx = tid + it * 256;
        int row = idx >> 3, k8 = idx & 7;
        const void* gp = (const char*)src + ((size_t)row * K_TOT + k0) * 2 + k8 * 16;
        cp_async16(dst_u32 + SMEM_SWIZZLE(row * 128 + k8 * 16), gp);
    }
}

// Pipelined mainloop: stages alternate between smem halves (32KB each: A|B).
__device__ __forceinline__ void gemm_mainloop(
    const MmaCtx& ctx, uint32_t smem_u32,
    const __nv_bfloat16* __restrict__ Ag, const __nv_bfloat16* __restrict__ Bg,
    int K_TOT, int tid, float acc[2][8][4])
{
    const int NS = K_TOT >> 6;
    // prologue: stage 0
    stage_tile_async(smem_u32,         Ag, K_TOT, 0, tid);
    stage_tile_async(smem_u32 + 16384, Bg, K_TOT, 0, tid);
    CP_COMMIT();
    for (int s = 0; s < NS; s++) {
        const uint32_t cur = smem_u32 + (s & 1) * 32768;
        if (s + 1 < NS) {
            const uint32_t nxt = smem_u32 + ((s + 1) & 1) * 32768;
            stage_tile_async(nxt,         Ag, K_TOT, (s + 1) << 6, tid);
            stage_tile_async(nxt + 16384, Bg, K_TOT, (s + 1) << 6, tid);
            CP_COMMIT();
            CP_WAIT_1();
        } else {
            CP_WAIT_0();
        }
        __syncthreads();
        mma_block_iter(ctx, cur, cur + 16384, acc);
        __syncthreads();
    }
}

// ============================================================================
// GEMM1: g16 = bf16(X16 @ WeT^T + be).  grid = (2, 128), 256 threads.
// ============================================================================
__global__ void __launch_bounds__(256) gemm1_mma_kernel(const float* __restrict__ be)
{
    extern __shared__ __align__(1024) char smem[];   // 65536 B: 2 stages x (A|B)
    __shared__ float bias_s[128];

    const int tid = threadIdx.x;
    const int warp = tid >> 5;
    const int rowBase = blockIdx.y * 128;
    const int colBase = blockIdx.x * 128;
    if (tid < 128) bias_s[tid] = be[colBase + tid];

    MmaCtx ctx; ctx.wm = warp & 3; ctx.wn = warp >> 2; ctx.lane = tid & 31;
    uint32_t smem_u32 = smem_u32_of(smem);

    float acc[2][8][4] = {};
    gemm_mainloop(ctx, smem_u32,
                  X16_buf + (size_t)rowBase * FDIM,
                  WeT16_buf + (size_t)colBase * FDIM, FDIM, tid, acc);

    // Epilogue: + bias, convert to bf16, store g16
    const int g = ctx.lane >> 2, q = ctx.lane & 3;
    #pragma unroll
    for (int mf = 0; mf < 2; mf++) {
        #pragma unroll
        for (int nf = 0; nf < 8; nf++) {
            int lcol = ctx.wn * 64 + nf * 8 + q * 2;
            int col  = colBase + lcol;
            float b0 = bias_s[lcol], b1 = bias_s[lcol + 1];
            int row0 = rowBase + ctx.wm * 32 + mf * 16 + g;
            __nv_bfloat162 h0 = __floats2bfloat162_rn(acc[mf][nf][0] + b0,
                                                      acc[mf][nf][1] + b1);
            __nv_bfloat162 h1 = __floats2bfloat162_rn(acc[mf][nf][2] + b0,
                                                      acc[mf][nf][3] + b1);
            *(__nv_bfloat162*)(g16_buf + (size_t)row0 * HDIM + col) = h0;
            *(__nv_bfloat162*)(g16_buf + (size_t)(row0 + 8) * HDIM + col) = h1;
        }
    }
}

// ============================================================================
// GEMM2 fused MSE: rec = g16 @ WdT^T + bd; accum (rec - X)^2.
// grid = (8, 128), 256 threads.
// ============================================================================
__global__ void __launch_bounds__(256) gemm2_mma_kernel(
    const float* __restrict__ bd, const float* __restrict__ X)
{
    extern __shared__ __align__(1024) char smem[];
    __shared__ float bias_s[128];
    __shared__ float red[256];

    const int tid = threadIdx.x;
    const int warp = tid >> 5;
    const int rowBase = blockIdx.y * 128;
    const int colBase = blockIdx.x * 128;
    if (tid < 128) bias_s[tid] = bd[colBase + tid];

    MmaCtx ctx; ctx.wm = warp & 3; ctx.wn = warp >> 2; ctx.lane = tid & 31;
    uint32_t smem_u32 = smem_u32_of(smem);

    float acc[2][8][4] = {};
    gemm_mainloop(ctx, smem_u32,
                  g16_buf + (size_t)rowBase * HDIM,
                  WdT16_buf + (size_t)colBase * HDIM, HDIM, tid, acc);

    // Fused epilogue: (acc + bd - X)^2
    const int g = ctx.lane >> 2, q = ctx.lane & 3;
    float local = 0.f;
    #pragma unroll
    for (int mf = 0; mf < 2; mf++) {
        #pragma unroll
        for (int nf = 0; nf < 8; nf++) {
            int lcol = ctx.wn * 64 + nf * 8 + q * 2;
            int col  = colBase + lcol;
            float b0 = bias_s[lcol], b1 = bias_s[lcol + 1];
            int row0 = rowBase + ctx.wm * 32 + mf * 16 + g;
            float2 x0 = *(const float2*)(X + (size_t)row0 * FDIM + col);
            float2 x1 = *(const float2*)(X + (size_t)(row0 + 8) * FDIM + col);
            float d0 = acc[mf][nf][0] + b0 - x0.x;
            float d1 = acc[mf][nf][1] + b1 - x0.y;
            float d2 = acc[mf][nf][2] + b0 - x1.x;
            float d3 = acc[mf][nf][3] + b1 - x1.y;
            local = fmaf(d0, d0, local);
            local = fmaf(d1, d1, local);
            local = fmaf(d2, d2, local);
            local = fmaf(d3, d3, local);
        }
    }

    red[tid] = local;
    __syncthreads();
    #pragma unroll
    for (int st = 128; st > 0; st >>= 1) {
        if (tid < st) red[tid] += red[tid + st];
        __syncthreads();
    }
    if (tid == 0) mse_partials[blockIdx.y * 8 + blockIdx.x] = red[0];
}

// ============================================================================
// Critic: c[i] = dot(g16[i,:], Wc) + bc.  One warp per row.
// ============================================================================
__global__ void __launch_bounds__(256) critic_kernel(
    const float* __restrict__ Wc, const float* __restrict__ bc)
{
    int row  = (blockIdx.x * 256 + threadIdx.x) >> 5;
    int lane = threadIdx.x & 31;
    int k0   = lane * 8;
    const __nv_bfloat162* gp =
        (const __nv_bfloat162*)(g16_buf + (size_t)row * HDIM + k0);
    float4 w0 = *(const float4*)(Wc + k0);
    float4 w1 = *(const float4*)(Wc + k0 + 4);
    float2 a0 = __bfloat1622float2(gp[0]);
    float2 a1 = __bfloat1622float2(gp[1]);
    float2 a2 = __bfloat1622float2(gp[2]);
    float2 a3 = __bfloat1622float2(gp[3]);
    float sum = a0.x * w0.x + a0.y * w0.y + a1.x * w0.z + a1.y * w0.w
              + a2.x * w1.x + a2.y * w1.y + a3.x * w1.z + a3.y * w1.w;
    #pragma unroll
    for (int off = 16; off > 0; off >>= 1)
        sum += __shfl_xor_sync(0xFFFFFFFFu, sum, off);
    if (lane == 0) c_buf[row] = sum + bc[0];
}

// ============================================================================
// Compaction: split c into c_prot (s==p) / c_rest (s!=p). 1 block, scan.
// ============================================================================
__global__ void __launch_bounds__(256) compact_kernel(
    const int* __restrict__ s, const int* __restrict__ p_ptr)
{
    __shared__ int scP[256], scR[256];
    const int tid = threadIdx.x;
    const int p = *p_ptr;
    const int base = tid * 64;

    int cp = 0;
    #pragma unroll 8
    for (int i = 0; i < 64; i++) cp += (s[base + i] == p) ? 1 : 0;
    scP[tid] = cp; scR[tid] = 64 - cp;
    __syncthreads();
    #pragma unroll
    for (int off = 1; off < 256; off <<= 1) {
        int vP = (tid >= off) ? scP[tid - off] : 0;
        int vR = (tid >= off) ? scR[tid - off] : 0;
        __syncthreads();
        scP[tid] += vP; scR[tid] += vR;
        __syncthreads();
    }
    if (tid == 255) { np_g = scP[255]; nr_g = scR[255]; }
    int oP = scP[tid] - cp;
    int oR = scR[tid] - (64 - cp);
    for (int i = 0; i < 64; i++) {
        int idx = base + i;
        float v = c_buf[idx];
        if (s[idx] == p) c_prot[oP++] = v;
        else             c_rest[oR++] = v;
    }
}

// ============================================================================
// Pairwise L1 over compacted arrays. grid (16,16), 4 i/thread, smem j tile.
// ============================================================================
__global__ void __launch_bounds__(256) pairwise_kernel()
{
    __shared__ float smj[1024];
    __shared__ float red[256];
    const int tid = threadIdx.x;
    const int np = np_g, nr = nr_g;
    const int iBase = blockIdx.x * 1024;
    const int jBase = blockIdx.y * 1024;

    float ci0 = 0.f, ci1 = 0.f, ci2 = 0.f, ci3 = 0.f;
    int i0 = iBase + tid, i1 = i0 + 256, i2 = i0 + 512, i3 = i0 + 768;
    bool v0 = i0 < np, v1 = i1 < np, v2 = i2 < np, v3 = i3 < np;
    if (v0) ci0 = c_prot[i0];
    if (v1) ci1 = c_prot[i1];
    if (v2) ci2 = c_prot[i2];
    if (v3) ci3 = c_prot[i3];

    #pragma unroll
    for (int t = tid; t < 1024; t += 256)
        smj[t] = (jBase + t < nr) ? c_rest[jBase + t] : 0.f;
    __syncthreads();

    int jn = nr - jBase;
    if (jn > 1024) jn = 1024;
    float a0 = 0.f, a1 = 0.f, a2 = 0.f, a3 = 0.f;
    for (int j = 0; j < jn; j++) {
        float cj = smj[j];
        a0 += fabsf(ci0 - cj);
        a1 += fabsf(ci1 - cj);
        a2 += fabsf(ci2 - cj);
        a3 += fabsf(ci3 - cj);
    }
    float local = (v0 ? a0 : 0.f) + (v1 ? a1 : 0.f) + (v2 ? a2 : 0.f) + (v3 ? a3 : 0.f);

    red[tid] = local;
    __syncthreads();
    #pragma unroll
    for (int st = 128; st > 0; st >>= 1) {
        if (tid < st) red[tid] += red[tid + st];
        __syncthreads();
    }
    if (tid == 0) pair_partials[blockIdx.y * 16 + blockIdx.x] = red[0];
}

// ============================================================================
// Finalize (1 block): reduce partials, write 4 outputs.
// ============================================================================
__global__ void __launch_bounds__(256) finalize_kernel(float* __restrict__ out)
{
    __shared__ double redd[256];
    const int tid = threadIdx.x;

    double m = 0.0;
    for (int i = tid; i < 1024; i += 256) m += (double)mse_partials[i];
    redd[tid] = m;
    __syncthreads();
    for (int st = 128; st > 0; st >>= 1) {
        if (tid < st) redd[tid] += redd[tid + st];
        __syncthreads();
    }
    double mse_sum = redd[0];
    __syncthreads();

    redd[tid] = (double)pair_partials[tid];
    __syncthreads();
    for (int st = 128; st > 0; st >>= 1) {
        if (tid < st) redd[tid] += redd[tid + st];
        __syncthreads();
    }
    double pair_sum = redd[0];

    if (tid == 0) {
        int count = np_g;
        out[0] = (float)(mse_sum / ((double)NROWS * (double)FDIM));
        out[1] = (float)NROWS;
        out[2] = (float)(pair_sum / (double)count);
        out[3] = (float)count;
    }
}

// ============================================================================
extern "C" void kernel_launch(void* const* d_in, const int* in_sizes, int n_in,
                              void* d_out, int out_size)
{
    const float* X  = (const float*)d_in[0];
    const float* We = (const float*)d_in[1];
    const float* be = (const float*)d_in[2];
    const float* Wd = (const float*)d_in[3];
    const float* bd = (const float*)d_in[4];
    const float* Wc = (const float*)d_in[5];
    const float* bc = (const float*)d_in[6];
    const int*   s  = (const int*)d_in[7];
    const int*   p  = (const int*)d_in[8];
    float* out = (float*)d_out;

    static bool attr_done = false;
    if (!attr_done) {
        cudaFuncSetAttribute(gemm1_mma_kernel,
            cudaFuncAttributeMaxDynamicSharedMemorySize, 65536);
        cudaFuncSetAttribute(gemm2_mma_kernel,
            cudaFuncAttributeMaxDynamicSharedMemorySize, 65536);
        attr_done = true;
    }

    conv_x_kernel<<<(NROWS * FDIM / 4) / 256, 256>>>(X);
    conv_w_kernel<<<(2 * HDIM * FDIM) / 256, 256>>>(We, Wd);

    gemm1_mma_kernel<<<dim3(2, NROWS / 128), 256, 65536>>>(be);
    gemm2_mma_kernel<<<dim3(8, NROWS / 128), 256, 65536>>>(bd, X);

    critic_kernel<<<(NROWS * 32) / 256, 256>>>(Wc, bc);
    compact_kernel<<<1, 256>>>(s, p);
    pairwise_kernel<<<dim3(16, 16), 256>>>();
    finalize_kernel<<<1, 256>>>(out);
}